// round 17
// baseline (speedup 1.0000x reference)
#include <cuda_runtime.h>

#define BB 256
#define II 1152
#define OO 10
#define DDO 16
#define DDI 8
#define OD 160       // OO*DDO
#define WPAD 12      // smem W row stride (floats), conflict-free LDS.128

#define IT 32        // i per block
#define NT 36        // II/IT
#define RPT 4        // i staged per sync round

// Scratch (device globals: allocation-free rule). No g_hat -- recomputed.
__device__ float g_spart[(size_t)BB * NT * OD];
__device__ float g_vsum[BB * OD];

// Fused pass: recompute hat_u = W @ x on the fly and do one routing step.
// pass 0: c = 1/10 uniform (no logits needed). pass >= 1: logits = hat.vsum,
// softmax over o (unstabilized, |logit| small), s_partial += c * hat.
// Lane = (og, d): o = og + 2j for j in 0..4.
__global__ void __launch_bounds__(256) k_pass(const float* __restrict__ x,
                                              const float* __restrict__ w,
                                              int pass) {
    __shared__ float wsm[RPT * 1920];
    __shared__ float vs[8][OD];
    const int t = threadIdx.x;
    const int warp = t >> 5, lane = t & 31;
    const int og = lane >> 4, d = lane & 15;
    const int i0 = blockIdx.x * IT;
    const int b0 = blockIdx.y * 8;
    const int b = b0 + warp;

    float vv[5];
    if (pass) {
        for (int m = t; m < 8 * OD; m += 256) vs[m / OD][m % OD] = g_vsum[b0 * OD + m];
        __syncthreads();
        #pragma unroll
        for (int j = 0; j < 5; j++) vv[j] = vs[warp][j * 32 + lane];
    }

    float sacc[5] = {0.f, 0.f, 0.f, 0.f, 0.f};

    for (int rr = 0; rr < IT / RPT; rr++) {
        const int ib = i0 + rr * RPT;
        #pragma unroll
        for (int im = 0; im < RPT; im++) {
            const float* wp = w + (size_t)(ib + im) * (OD * DDI);
            float* ws = wsm + im * 1920;
            #pragma unroll
            for (int r = 0; r < 5; r++) {
                int e = t + r * 256;                  // 0..1279 = od*8+k
                ws[(e >> 3) * WPAD + (e & 7)] = wp[e];
            }
        }
        __syncthreads();

        #pragma unroll
        for (int im = 0; im < RPT; im++) {
            const int i = ib + im;
            const float* xp = x + ((size_t)b * II + i) * DDI;
            const float4 xa = *(const float4*)xp;
            const float4 xb = *(const float4*)(xp + 4);
            const float* base = wsm + im * 1920;

            float h[5];
            #pragma unroll
            for (int j = 0; j < 5; j++) {
                const float* wr = base + ((og + 2 * j) * DDO + d) * WPAD;
                const float4 wa = *(const float4*)wr;
                const float4 wb = *(const float4*)(wr + 4);
                h[j] = wa.x*xa.x + wa.y*xa.y + wa.z*xa.z + wa.w*xa.w
                     + wb.x*xb.x + wb.y*xb.y + wb.z*xb.z + wb.w*xb.w;
            }

            if (pass) {
                float q[5];
                #pragma unroll
                for (int j = 0; j < 5; j++) q[j] = h[j] * vv[j];
                #pragma unroll
                for (int s = 8; s >= 1; s >>= 1) {
                    #pragma unroll
                    for (int j = 0; j < 5; j++)
                        q[j] += __shfl_xor_sync(0xffffffffu, q[j], s);
                }
                float e[5], se = 0.f;
                #pragma unroll
                for (int j = 0; j < 5; j++) { e[j] = __expf(q[j]); se += e[j]; }
                const float tot = se + __shfl_xor_sync(0xffffffffu, se, 16);
                const float rt = 1.0f / tot;
                #pragma unroll
                for (int j = 0; j < 5; j++) sacc[j] += (e[j] * rt) * h[j];
            } else {
                #pragma unroll
                for (int j = 0; j < 5; j++) sacc[j] += h[j];
            }
        }
        __syncthreads();
    }

    const float sc = pass ? 1.0f : 0.1f;
    float* sp = g_spart + ((size_t)b * NT + blockIdx.x) * OD;
    #pragma unroll
    for (int j = 0; j < 5; j++) sp[j * 32 + lane] = sc * sacc[j];
}

// Squash: fixed-order partial reduction over NT tiles. Warp per (b,o).
// mode 0: vsum = v ; mode 1: vsum += v ; mode 2: out = v
__global__ void __launch_bounds__(256) k_squash(float* __restrict__ out, int mode) {
    const int t = threadIdx.x;
    const int warp = t >> 5, lane = t & 31;
    const int g = blockIdx.x * 8 + warp;       // (b,o), 2560 total
    const int d = lane & 15, tc = lane >> 4;
    const int b = g / OO, o = g - b * OO;
    const int od = o * DDO + d;

    float sh = 0.f;
    for (int tt = tc; tt < NT; tt += 2)
        sh += g_spart[((size_t)b * NT + tt) * OD + od];
    const float s = sh + __shfl_xor_sync(0xffffffffu, sh, 16);

    float ss = s * s;
    #pragma unroll
    for (int r = 8; r >= 1; r >>= 1)
        ss += __shfl_xor_sync(0xffffffffu, ss, r);

    const float nrm = sqrtf(ss);
    const float v = s * (nrm / (nrm * nrm + 1.0f));
    if (tc == 0) {
        const int idx = b * OD + od;
        if (mode == 2)      out[idx] = v;
        else if (mode == 1) g_vsum[idx] += v;
        else                g_vsum[idx] = v;
    }
}

extern "C" void kernel_launch(void* const* d_in, const int* in_sizes, int n_in,
                              void* d_out, int out_size) {
    const float* x = (const float*)d_in[0];   // (B, I, DI)
    const float* w = (const float*)d_in[1];   // (I*O, DO, DI)
    float* out = (float*)d_out;               // (B, O, DO)

    dim3 grid(NT, BB / 8);

    k_pass<<<grid, 256>>>(x, w, 0);        // s0 = 0.1 * sum_i hat
    k_squash<<<320, 256>>>(out, 0);        // v0 -> vsum
    k_pass<<<grid, 256>>>(x, w, 1);        // iter 1 (recompute hat)
    k_squash<<<320, 256>>>(out, 1);        // v1 -> vsum
    k_pass<<<grid, 256>>>(x, w, 2);        // iter 2 (recompute hat)
    k_squash<<<320, 256>>>(out, 2);        // v2 -> out
}